// round 9
// baseline (speedup 1.0000x reference)
#include <cuda_runtime.h>
#include <math.h>

// Problem constants
#define BB   64
#define NN   100
#define LL   32
#define RR   (BB*NN)     // 6400 rows
#define EH   64          // edge hidden / edge out width
#define NHID 64          // node hidden
#define NOUT 32          // node out (== LL)
#define ALPHA 0.1f

// Scratch (static device globals — no allocations allowed)
// s/v are double-buffered: k_edge step s reads buf s&1? -> we ping-pong 0->1.
__device__ float g_h   [RR*LL];          // node features
__device__ float g_s   [2][RR*EH];       // layer-0 "i" part (u_i + b0)
__device__ float g_v   [2][RR*EH];       // layer-0 "j" part
__device__ float g_dist[BB*NN*NN];       // pairwise distances per batch

__device__ __forceinline__ float lrelu(float x) { return x > 0.f ? x : ALPHA * x; }

#define FMA_F32X2(d, a, b, c) \
    asm("fma.rn.f32x2 %0, %1, %2, %3;" : "=l"(d) : "l"(a), "l"(b), "l"(c))

// ---------------------------------------------------------------------------
// h = (x @ lin_w + lin_b)   fused with   prep for step 0 (s/v into buf 0).
// One block per batch element, 256 threads.
// ---------------------------------------------------------------------------
__global__ void k_lin_prep(const float* __restrict__ x,
                           const float* __restrict__ lw,
                           const float* __restrict__ lb,
                           const float* __restrict__ w0,
                           const float* __restrict__ b0)
{
    __shared__ float xs[LL];
    __shared__ float hs[NN*LL];
    const int bb = blockIdx.x;
    const int tid = threadIdx.x;
    if (tid < LL) xs[tid] = x[bb*LL + tid];
    __syncthreads();
    for (int col = tid; col < NN*LL; col += 256) {
        float acc = lb[col];
        #pragma unroll
        for (int k = 0; k < LL; k++)
            acc += xs[k] * lw[k*(NN*LL) + col];
        hs[col] = acc;
        g_h[bb*NN*LL + col] = acc;
    }
    __syncthreads();
    // prep step 0: per (local row j, col c)
    for (int idx = tid; idx < NN*EH; idx += 256) {
        const int j = idx >> 6;
        const int c = idx & 63;
        float su = b0[c], sv = 0.f;
        const float* hr = &hs[j*LL];
        #pragma unroll
        for (int k = 0; k < LL; k++) {
            const float hk = hr[k];
            su += hk * w0[k*EH + c];
            sv += hk * w0[(LL + k)*EH + c];
        }
        const int r = bb*NN + j;
        g_s[0][r*EH + c] = su;
        g_v[0][r*EH + c] = sv;
    }
}

// ---------------------------------------------------------------------------
// Pairwise distances: dist[b,i,j] = sqrt(||h_i - h_j||^2 + 1e-12)
// ---------------------------------------------------------------------------
__global__ void k_dist()
{
    const int bb    = blockIdx.x >> 2;
    const int chunk = blockIdx.x & 3;
    __shared__ float hs[NN*LL];
    for (int idx = threadIdx.x; idx < NN*LL; idx += blockDim.x)
        hs[idx] = g_h[bb*NN*LL + idx];
    __syncthreads();
    const int i0 = chunk * 25;
    for (int idx = threadIdx.x; idx < 25*NN; idx += blockDim.x) {
        const int i = i0 + idx / NN;
        const int j = idx % NN;
        const float* hi = &hs[i*LL];
        const float* hj = &hs[j*LL];
        float d2 = 1e-12f;
        #pragma unroll
        for (int k = 0; k < LL; k++) {
            const float dk = hi[k] - hj[k];
            d2 += dk * dk;
        }
        g_dist[bb*NN*NN + i*NN + j] = sqrtf(d2);
    }
}

// ---------------------------------------------------------------------------
// Edge MLP + aggregation + (fused) node MLP + (fused) next-prep or output.
//
// One block per (b,i), 128 threads.
//   Phase 1: t[j][k] = lrelu(s_i[k] + v_j[k] + dist_ij*wd[k]), j-major, stride 65.
//   Phase 2: 8x8 register tile of t @ W1, inner loop on the packed-fp32 pipe:
//            4 FFMA2 per t-value (cols packed in natural LDS.128 64-bit lanes,
//            t splat via mov.b64 {r,r}).
//   Tail:    reduce agg over 16 jg partials, then node MLP for row r; writes
//            either (g_h + next-step s/v into buf) or tanh(out head) to d_out.
// ---------------------------------------------------------------------------
#define TROWS 104
#define TS    65

__global__ void __launch_bounds__(128) k_edge(
    const float* __restrict__ w0,  const float* __restrict__ w1,
    const float* __restrict__ b1,
    const float* __restrict__ nw0, const float* __restrict__ nb0,
    const float* __restrict__ nw1, const float* __restrict__ nb1,
    const float* __restrict__ nxt_w0, const float* __restrict__ nxt_b0,
    const float* __restrict__ ow,  const float* __restrict__ ob,
    float* __restrict__ out,
    int sbuf, int final_step)
{
    __shared__ float sh_t [TROWS * TS];  // 27.0 KB
    __shared__ float sh_w1[EH * EH];     // 16 KB
    __shared__ float sh_dist[NN];
    __shared__ float sh_s[EH], sh_wd[EH], sh_b1[EH];
    __shared__ float sh_in[LL + EH];     // node MLP input [h, agg]
    __shared__ float sh_hid[NHID];
    __shared__ float sh_hn[NOUT];

    const int tid = threadIdx.x;
    const int r   = blockIdx.x;          // b*100 + i
    const int bb  = r / NN;
    const int i   = r - bb*NN;

    for (int idx = tid; idx < EH*EH; idx += 128) sh_w1[idx] = w1[idx];
    if (tid < NN) sh_dist[tid] = g_dist[bb*NN*NN + i*NN + tid];
    if (tid < EH) {
        sh_s [tid] = g_s[sbuf][r*EH + tid];
        sh_wd[tid] = w0[(2*LL)*EH + tid];   // row 64 of W0: dist weights
        sh_b1[tid] = b1[tid];
    }
    if (tid < LL) sh_in[tid] = g_h[r*LL + tid];
    __syncthreads();

    // Phase 1
    const float* vbase = &g_v[sbuf][bb*NN*EH];
    for (int idx = tid; idx < NN*EH; idx += 128) {
        const int j = idx >> 6;
        const int c = idx & 63;
        const float t = sh_s[c] + vbase[idx] + sh_dist[j] * sh_wd[c];
        sh_t[j*TS + c] = lrelu(t);
    }
    __syncthreads();

    // Phase 2: 8x8 tile, packed-fp32 inner loop
    const int cg = tid & 7;
    const int jg = tid >> 3;
    const int c0 = cg * 8;
    const int j0 = jg * 8;
    const int j0c = (j0 <= TROWS - 8) ? j0 : (TROWS - 8);
    const float* tb = &sh_t[j0c * TS];

    unsigned long long acc2[8][4];
    #pragma unroll
    for (int u = 0; u < 8; u++)
        #pragma unroll
        for (int v = 0; v < 4; v++) acc2[u][v] = 0ull;   // two +0.0f lanes

    #pragma unroll 4
    for (int k = 0; k < EH; k++) {
        // cols c0..c0+7 as 4 natural 64-bit pairs (low lane = even col)
        const ulonglong2 wA = *reinterpret_cast<const ulonglong2*>(&sh_w1[k*EH + c0]);
        const ulonglong2 wB = *reinterpret_cast<const ulonglong2*>(&sh_w1[k*EH + c0 + 4]);
        #pragma unroll
        for (int u = 0; u < 8; u++) {
            const unsigned int tbits = __float_as_uint(tb[u*TS + k]);
            unsigned long long t2;
            asm("mov.b64 %0, {%1, %1};" : "=l"(t2) : "r"(tbits));
            FMA_F32X2(acc2[u][0], t2, wA.x, acc2[u][0]);
            FMA_F32X2(acc2[u][1], t2, wA.y, acc2[u][1]);
            FMA_F32X2(acc2[u][2], t2, wB.x, acc2[u][2]);
            FMA_F32X2(acc2[u][3], t2, wB.y, acc2[u][3]);
        }
    }

    // Epilogue: unpack, bias + leaky, accumulate over valid j's
    float bv[8];
    #pragma unroll
    for (int v = 0; v < 8; v++) bv[v] = sh_b1[c0 + v];

    float part[8];
    #pragma unroll
    for (int v = 0; v < 8; v++) part[v] = 0.f;
    #pragma unroll
    for (int u = 0; u < 8; u++) {
        if (j0 + u < NN) {
            #pragma unroll
            for (int v = 0; v < 4; v++) {
                const unsigned long long a = acc2[u][v];
                const float lo = __uint_as_float((unsigned int)(a));
                const float hi = __uint_as_float((unsigned int)(a >> 32));
                part[2*v]     += lrelu(lo + bv[2*v]);
                part[2*v + 1] += lrelu(hi + bv[2*v + 1]);
            }
        }
    }

    // Reduce 16 jg partials (reuse sh_t)
    __syncthreads();
    float* red = sh_t;
    #pragma unroll
    for (int v = 0; v < 8; v++) red[jg*64 + c0 + v] = part[v];
    __syncthreads();
    if (tid < EH) {
        float s = 0.f;
        #pragma unroll
        for (int g = 0; g < 16; g++) s += red[g*64 + tid];
        sh_in[LL + tid] = s;
    }
    __syncthreads();

    // Fused node MLP: hid = lrelu([h, agg] @ nw0 + nb0)
    if (tid < NHID) {
        float a = nb0[tid];
        #pragma unroll 8
        for (int k = 0; k < LL + EH; k++)
            a += sh_in[k] * nw0[k*NHID + tid];
        sh_hid[tid] = lrelu(a);
    }
    __syncthreads();
    // h_new = lrelu(hid @ nw1 + nb1)
    if (tid < NOUT) {
        float o = nb1[tid];
        #pragma unroll 8
        for (int k = 0; k < NHID; k++)
            o += sh_hid[k] * nw1[k*NOUT + tid];
        const float hn = lrelu(o);
        sh_hn[tid] = hn;
        if (!final_step) g_h[r*LL + tid] = hn;
    }
    __syncthreads();

    if (final_step) {
        // out = tanh(h_new @ ow + ob), 3 outputs
        if (tid < 3) {
            float a = ob[tid];
            #pragma unroll
            for (int k = 0; k < NOUT; k++)
                a += sh_hn[k] * ow[k*3 + tid];
            out[r*3 + tid] = tanhf(a);
        }
    } else {
        // prep for next step into the other s/v buffer
        if (tid < EH) {
            float su = nxt_b0[tid], sv = 0.f;
            #pragma unroll
            for (int k = 0; k < LL; k++) {
                const float hk = sh_hn[k];
                su += hk * nxt_w0[k*EH + tid];
                sv += hk * nxt_w0[(LL + k)*EH + tid];
            }
            g_s[sbuf ^ 1][r*EH + tid] = su;
            g_v[sbuf ^ 1][r*EH + tid] = sv;
        }
    }
}

// ---------------------------------------------------------------------------
// Launch — 5 kernels total, graph-capturable, allocation-free
// ---------------------------------------------------------------------------
extern "C" void kernel_launch(void* const* d_in, const int* in_sizes, int n_in,
                              void* d_out, int out_size)
{
    const float* x  = (const float*)d_in[0];
    const float* lw = (const float*)d_in[1];
    const float* lb = (const float*)d_in[2];
    const float* ew0[2] = { (const float*)d_in[3],  (const float*)d_in[11] };
    const float* eb0[2] = { (const float*)d_in[4],  (const float*)d_in[12] };
    const float* ew1[2] = { (const float*)d_in[5],  (const float*)d_in[13] };
    const float* eb1[2] = { (const float*)d_in[6],  (const float*)d_in[14] };
    const float* nw0[2] = { (const float*)d_in[7],  (const float*)d_in[15] };
    const float* nb0[2] = { (const float*)d_in[8],  (const float*)d_in[16] };
    const float* nw1[2] = { (const float*)d_in[9],  (const float*)d_in[17] };
    const float* nb1[2] = { (const float*)d_in[10], (const float*)d_in[18] };
    const float* ow = (const float*)d_in[19];
    const float* ob = (const float*)d_in[20];
    float* out = (float*)d_out;

    k_lin_prep<<<BB, 256>>>(x, lw, lb, ew0[0], eb0[0]);

    k_dist<<<BB*4, 256>>>();
    k_edge<<<RR, 128>>>(ew0[0], ew1[0], eb1[0],
                        nw0[0], nb0[0], nw1[0], nb1[0],
                        ew0[1], eb0[1],
                        nullptr, nullptr, nullptr,
                        0, 0);

    k_dist<<<BB*4, 256>>>();
    k_edge<<<RR, 128>>>(ew0[1], ew1[1], eb1[1],
                        nw0[1], nb0[1], nw1[1], nb1[1],
                        nullptr, nullptr,
                        ow, ob, out,
                        1, 1);
}